// round 3
// baseline (speedup 1.0000x reference)
#include <cuda_runtime.h>
#include <cstdint>

#define TPB 256

// Output tuple layout (flattened, in reference return order)
static const size_t OFF_QUANT = 1;                       // [32,128,32,32]
static const size_t OFF_PERP  = 4194305;                 // scalar
static const size_t OFF_ENC   = 4194306;                 // [32768,1024]
static const size_t OFF_TOPK  = 37748738;                // [3,32,32,32,128]

__device__ float g_enorm[1024];
__device__ float g_loss_sum;
__device__ int   g_counts[1024];

// ---------------------------------------------------------------------------
// Init: embedding row norms, zero counters
// ---------------------------------------------------------------------------
__global__ void k_init(const float* __restrict__ emb) {
    int gtid = blockIdx.x * blockDim.x + threadIdx.x;
    int w = gtid >> 5;
    int lane = gtid & 31;
    if (w < 1024) {
        float4 v = ((const float4*)(emb + (size_t)w * 128))[lane];
        float s = v.x*v.x + v.y*v.y + v.z*v.z + v.w*v.w;
        #pragma unroll
        for (int o = 16; o; o >>= 1) s += __shfl_down_sync(0xffffffffu, s, o);
        if (lane == 0) { g_enorm[w] = s; g_counts[w] = 0; }
    }
    if (gtid == 0) g_loss_sum = 0.0f;
}

// ---------------------------------------------------------------------------
// Zero-fill encodings region (only 8B-aligned -> float2)
// ---------------------------------------------------------------------------
__global__ void k_zero(float2* __restrict__ p, int n2) {
    int i = blockIdx.x * blockDim.x + threadIdx.x;
    int s = gridDim.x * blockDim.x;
    float2 z = make_float2(0.f, 0.f);
    for (; i < n2; i += s) p[i] = z;
}

// ---------------------------------------------------------------------------
// Sortable packing: monotone float->uint, idx in low bits (stable ties = lower idx)
// ---------------------------------------------------------------------------
__device__ __forceinline__ unsigned long long packkey(float k, int idx) {
    unsigned u = __float_as_uint(k);
    u = (u & 0x80000000u) ? ~u : (u | 0x80000000u);
    return ((unsigned long long)u << 32) | (unsigned)idx;
}

__device__ __forceinline__ void ins3(unsigned long long pk,
                                     unsigned long long& a0,
                                     unsigned long long& a1,
                                     unsigned long long& a2) {
    if (pk < a2) {
        if (pk < a1) {
            a2 = a1;
            if (pk < a0) { a1 = a0; a0 = pk; } else { a1 = pk; }
        } else {
            a2 = pk;
        }
    }
}

#define XS_STRIDE 65
#define ES_STRIDE 133
#define SMEM_FLOATS (128*XS_STRIDE + 128*ES_STRIDE)
#define SMEM_BYTES  (SMEM_FLOATS*4 + 64*3*4 + 8*4)

// ---------------------------------------------------------------------------
// Main kernel: per block 64 points, full 1024-emb loop in 8 tiles of 128.
// Warp-uniform point groups (8 pts/warp). Thread micro-tile: 8 pts x 4 embs
// (embs strided by 32 lanes -> conflict-free smem reads).
// ---------------------------------------------------------------------------
__global__ void __launch_bounds__(TPB) k_main(const float* __restrict__ inp,
                                              const float* __restrict__ emb,
                                              float* __restrict__ out) {
    extern __shared__ float sm[];
    float* xs = sm;                         // [128][65]   x tile, kk-major
    float* es = sm + 128 * XS_STRIDE;       // [128][133]  e tile, kk-major
    int*   sidx = (int*)(sm + SMEM_FLOATS); // [64][3]
    float* sred = (float*)(sidx + 64 * 3);  // [8]

    const int t    = threadIdx.x;
    const int lane = t & 31;
    const int wid  = t >> 5;
    const int n0   = blockIdx.x * 64;
    const int b    = n0 >> 10;
    const int hw0  = n0 & 1023;
    const float* inbase = inp + (size_t)b * 131072 + hw0;

    // Load x tile transposed: xs[kk][p] = inputs[b][kk][hw0+p]  (coalesced)
    for (int i = t; i < 128 * 64; i += TPB) {
        int kk = i >> 6, p = i & 63;
        xs[kk * XS_STRIDE + p] = inbase[(size_t)kk * 1024 + p];
    }

    unsigned long long b0[8], b1[8], b2[8];
    #pragma unroll
    for (int i = 0; i < 8; i++) { b0[i] = ~0ULL; b1[i] = ~0ULL; b2[i] = ~0ULL; }

    for (int tl = 0; tl < 8; tl++) {
        __syncthreads();
        // Load e tile transposed: es[kk][e]. Global reads coalesced (q along
        // lanes), smem stores conflict-free (stride 133: bank = 5*q+e bijective).
        for (int i = t; i < 128 * 32; i += TPB) {
            int e = i >> 5, q = i & 31;
            const float* g = emb + ((size_t)(tl * 128 + e)) * 128 + q;
            es[(q      ) * ES_STRIDE + e] = g[0];
            es[(q + 32 ) * ES_STRIDE + e] = g[32];
            es[(q + 64 ) * ES_STRIDE + e] = g[64];
            es[(q + 96 ) * ES_STRIDE + e] = g[96];
        }
        __syncthreads();

        float acc[8][4];
        #pragma unroll
        for (int i = 0; i < 8; i++) {
            acc[i][0] = 0.f; acc[i][1] = 0.f; acc[i][2] = 0.f; acc[i][3] = 0.f;
        }

        const float* xw = xs + wid * 8;
        #pragma unroll 4
        for (int kk = 0; kk < 128; kk++) {
            const float* er = es + kk * ES_STRIDE + lane;
            float e0 = er[0], e1 = er[32], e2 = er[64], e3 = er[96];
            const float* xr = xw + kk * XS_STRIDE;
            #pragma unroll
            for (int i = 0; i < 8; i++) {
                float xv = xr[i];
                acc[i][0] = fmaf(xv, e0, acc[i][0]);
                acc[i][1] = fmaf(xv, e1, acc[i][1]);
                acc[i][2] = fmaf(xv, e2, acc[i][2]);
                acc[i][3] = fmaf(xv, e3, acc[i][3]);
            }
        }

        // Ranking key: ||e||^2 - 2*dot (||x||^2 constant per point, dropped)
        int ib = tl * 128 + lane;
        float n0v = g_enorm[ib], n1v = g_enorm[ib + 32];
        float n2v = g_enorm[ib + 64], n3v = g_enorm[ib + 96];
        #pragma unroll
        for (int i = 0; i < 8; i++) {
            ins3(packkey(n0v - 2.f * acc[i][0], ib     ), b0[i], b1[i], b2[i]);
            ins3(packkey(n1v - 2.f * acc[i][1], ib + 32), b0[i], b1[i], b2[i]);
            ins3(packkey(n2v - 2.f * acc[i][2], ib + 64), b0[i], b1[i], b2[i]);
            ins3(packkey(n3v - 2.f * acc[i][3], ib + 96), b0[i], b1[i], b2[i]);
        }
    }

    // Warp-level top3 merge (order-independent min-3 over total order)
    #pragma unroll
    for (int off = 16; off; off >>= 1) {
        #pragma unroll
        for (int i = 0; i < 8; i++) {
            unsigned long long x0 = __shfl_down_sync(0xffffffffu, b0[i], off);
            unsigned long long x1 = __shfl_down_sync(0xffffffffu, b1[i], off);
            unsigned long long x2 = __shfl_down_sync(0xffffffffu, b2[i], off);
            ins3(x0, b0[i], b1[i], b2[i]);
            ins3(x1, b0[i], b1[i], b2[i]);
            ins3(x2, b0[i], b1[i], b2[i]);
        }
    }
    if (lane == 0) {
        #pragma unroll
        for (int i = 0; i < 8; i++) {
            int p = wid * 8 + i;
            sidx[p * 3 + 0] = (int)(b0[i] & 0xffffffffu);
            sidx[p * 3 + 1] = (int)(b1[i] & 0xffffffffu);
            sidx[p * 3 + 2] = (int)(b2[i] & 0xffffffffu);
        }
    }
    __syncthreads();

    // encodings one-hot (3rd nearest) + counts for perplexity
    if (t < 64) {
        int i3 = sidx[t * 3 + 2];
        out[OFF_ENC + (size_t)(n0 + t) * 1024 + i3] = 1.0f;
        atomicAdd(&g_counts[i3], 1);
    }

    // quantized_nchw (nearest) + loss accumulation
    float lsum = 0.f;
    {
        int p  = t & 63;
        int d0 = t >> 6;
        int i0 = sidx[p * 3 + 0];
        const float* e0r = emb + (size_t)i0 * 128;
        size_t qb = OFF_QUANT + (size_t)b * 131072 + (size_t)hw0 + p;
        #pragma unroll
        for (int j = 0; j < 32; j++) {
            int d = d0 + 4 * j;
            float x  = xs[d * XS_STRIDE + p];
            float df = e0r[d] - x;
            lsum += df * df;
            out[qb + (size_t)d * 1024] = x + df;   // straight-through: x + (q0 - x)
        }
    }
    #pragma unroll
    for (int o = 16; o; o >>= 1) lsum += __shfl_down_sync(0xffffffffu, lsum, o);
    if (lane == 0) sred[wid] = lsum;
    __syncthreads();
    if (t == 0) {
        float s = 0.f;
        #pragma unroll
        for (int i = 0; i < 8; i++) s += sred[i];
        atomicAdd(&g_loss_sum, s);
    }

    // top_k_quantized: [3, N, 128], contiguous in d -> lanes sweep d
    {
        int d  = t & 127;
        int pg = t >> 7;
        #pragma unroll
        for (int k = 0; k < 3; k++) {
            size_t kb = OFF_TOPK + ((size_t)k * 32768 + (size_t)n0) * 128 + d;
            for (int ii = 0; ii < 32; ii++) {
                int p   = pg + 2 * ii;
                int idx = sidx[p * 3 + k];
                float x = xs[d * XS_STRIDE + p];
                float v = x + (emb[(size_t)idx * 128 + d] - x);
                out[kb + (size_t)p * 128] = v;
            }
        }
    }
}

// ---------------------------------------------------------------------------
// Finalize: loss scalar + perplexity
// ---------------------------------------------------------------------------
__global__ void k_final(float* __restrict__ out) {
    __shared__ float red[32];
    int t = threadIdx.x;   // 1024 threads
    float p = (float)g_counts[t] * (1.0f / 32768.0f);
    float v = p * logf(p + 1e-10f);
    #pragma unroll
    for (int o = 16; o; o >>= 1) v += __shfl_down_sync(0xffffffffu, v, o);
    if ((t & 31) == 0) red[t >> 5] = v;
    __syncthreads();
    if (t < 32) {
        float s = red[t];
        #pragma unroll
        for (int o = 16; o; o >>= 1) s += __shfl_down_sync(0xffffffffu, s, o);
        if (t == 0) {
            out[OFF_PERP] = expf(-s);
            out[0] = 0.25f * g_loss_sum * (1.0f / 4194304.0f);
        }
    }
}

// ---------------------------------------------------------------------------
extern "C" void kernel_launch(void* const* d_in, const int* in_sizes, int n_in,
                              void* d_out, int out_size) {
    const float* inp = (const float*)d_in[0];   // [32,128,32,32] fp32
    const float* emb = (const float*)d_in[1];   // [1024,128]    fp32
    float* out = (float*)d_out;

    cudaFuncSetAttribute(k_main, cudaFuncAttributeMaxDynamicSharedMemorySize, SMEM_BYTES);

    k_init<<<128, 256>>>(emb);
    k_zero<<<2048, 256>>>((float2*)(out + OFF_ENC), 33554432 / 2);
    k_main<<<512, 256, SMEM_BYTES>>>(inp, emb, out);
    k_final<<<1, 1024>>>(out);
}

// round 5
// speedup vs baseline: 1.3194x; 1.3194x over previous
#include <cuda_runtime.h>
#include <cuda_bf16.h>
#include <cstdint>

// ---------------------------------------------------------------------------
// Output tuple layout (flattened, reference return order)
// ---------------------------------------------------------------------------
static const size_t OFF_QUANT = 1;         // [32,128,32,32]
static const size_t OFF_PERP  = 4194305;   // scalar
static const size_t OFF_ENC   = 4194306;   // [32768,1024]
static const size_t OFF_TOPK  = 37748738;  // [3,32,32,32,128]

__device__ float g_enorm[1024];
__device__ float g_loss_sum;
__device__ int   g_counts[1024];
// bf16 codebook, rows of 256B, pre-swizzled for ldmatrix (chunk c ^= row&7)
__device__ __align__(16) unsigned char g_embbf[1024 * 256];

// ---------------------------------------------------------------------------
// helpers
// ---------------------------------------------------------------------------
__device__ __forceinline__ uint32_t smem_u32(const void* p) {
    uint32_t a;
    asm("{ .reg .u64 t; cvta.to.shared.u64 t, %1; cvt.u32.u64 %0, t; }" : "=r"(a) : "l"(p));
    return a;
}
// swizzled byte offset within a [row][k] bf16 tile (256B rows, 16B chunks)
__device__ __forceinline__ uint32_t swoff(int row, int k) {
    return (uint32_t)(row * 256 + ((((k >> 3) ^ (row & 7)) << 4)) + (k & 7) * 2);
}

#define CP_ASYNC16(dst, src) asm volatile("cp.async.ca.shared.global [%0], [%1], 16;" :: "r"(dst), "l"(src) : "memory")
#define CP_COMMIT()          asm volatile("cp.async.commit_group;" ::: "memory")
#define CP_WAIT1()           asm volatile("cp.async.wait_group 1;" ::: "memory")
#define CP_WAIT0()           asm volatile("cp.async.wait_group 0;" ::: "memory")

__device__ __forceinline__ void ldsm4(uint32_t r[4], uint32_t addr) {
    asm volatile("ldmatrix.sync.aligned.m8n8.x4.shared.b16 {%0,%1,%2,%3}, [%4];"
                 : "=r"(r[0]), "=r"(r[1]), "=r"(r[2]), "=r"(r[3]) : "r"(addr));
}
__device__ __forceinline__ void mma16816(float& d0, float& d1, float& d2, float& d3,
                                         const uint32_t a[4], uint32_t b0, uint32_t b1) {
    asm volatile("mma.sync.aligned.m16n8k16.row.col.f32.bf16.bf16.f32 "
                 "{%0,%1,%2,%3},{%4,%5,%6,%7},{%8,%9},{%0,%1,%2,%3};"
                 : "+f"(d0), "+f"(d1), "+f"(d2), "+f"(d3)
                 : "r"(a[0]), "r"(a[1]), "r"(a[2]), "r"(a[3]), "r"(b0), "r"(b1));
}

__device__ __forceinline__ unsigned long long packkey(float k, int idx) {
    unsigned u = __float_as_uint(k);
    u = (u & 0x80000000u) ? ~u : (u | 0x80000000u);
    return ((unsigned long long)u << 32) | (unsigned)idx;
}
__device__ __forceinline__ void ins3(unsigned long long pk,
                                     unsigned long long& a0, unsigned long long& a1,
                                     unsigned long long& a2) {
    if (pk < a2) {
        if (pk < a1) { a2 = a1; if (pk < a0) { a1 = a0; a0 = pk; } else a1 = pk; }
        else a2 = pk;
    }
}
__device__ __forceinline__ void ins4f(float k, int e,
                                      float& k0, int& i0, float& k1, int& i1,
                                      float& k2, int& i2, float& k3, int& i3) {
    if (k < k3) {
        if (k < k1) {
            k3 = k2; i3 = i2; k2 = k1; i2 = i1;
            if (k < k0) { k1 = k0; i1 = i0; k0 = k; i0 = e; } else { k1 = k; i1 = e; }
        } else {
            if (k < k2) { k3 = k2; i3 = i2; k2 = k; i2 = e; } else { k3 = k; i3 = e; }
        }
    }
}

// ---------------------------------------------------------------------------
// SMEM layout (bytes)
// ---------------------------------------------------------------------------
#define SM_XP    0u        // float [128 p][132 d]  (67584B); 16B-aligned rows
#define SM_A     68608u    // bf16 A tile 32KB (swizzled); ES fp32 [128][132] reuses A..B1
#define SM_B0    101376u   // bf16 B buf 32KB
#define SM_B1    134144u   // bf16 B buf 32KB
#define SM_EN    166912u   // float [1024]
#define SM_CI    171008u   // int  [128][16]
#define SM_PK    179200u   // u64  [128][16]
#define SM_SIDX  195584u   // int  [128][3]
#define SMEM_TOTAL 197120u

// ---------------------------------------------------------------------------
__global__ void k_init(const float* __restrict__ emb) {
    int gtid = blockIdx.x * blockDim.x + threadIdx.x;
    int w = gtid >> 5, lane = gtid & 31;
    if (w < 1024) {
        float4 v = ((const float4*)(emb + (size_t)w * 128))[lane];
        __nv_bfloat162 p0 = __floats2bfloat162_rn(v.x, v.y);
        __nv_bfloat162 p1 = __floats2bfloat162_rn(v.z, v.w);
        uint32_t byte = swoff(w, lane * 4);
        *(uint2*)(g_embbf + byte) =
            make_uint2(*(uint32_t*)&p0, *(uint32_t*)&p1);
        float s = v.x*v.x + v.y*v.y + v.z*v.z + v.w*v.w;
        #pragma unroll
        for (int o = 16; o; o >>= 1) s += __shfl_down_sync(0xffffffffu, s, o);
        if (lane == 0) { g_enorm[w] = s; g_counts[w] = 0; }
    }
    if (gtid == 0) g_loss_sum = 0.0f;
}

// ---------------------------------------------------------------------------
__global__ void __launch_bounds__(256) k_main(const float* __restrict__ inp,
                                              const float* __restrict__ emb,
                                              float* __restrict__ out) {
    extern __shared__ char smem[];
    const uint32_t sb = smem_u32(smem);
    float* XP = (float*)(smem + SM_XP);
    float* EN = (float*)(smem + SM_EN);
    int*   CI = (int*)(smem + SM_CI);
    unsigned long long* PK = (unsigned long long*)(smem + SM_PK);
    int*   SIDX = (int*)(smem + SM_SIDX);

    const int t    = threadIdx.x;
    const int lane = t & 31;
    const int wid  = t >> 5;
    const int n0   = blockIdx.x * 128;
    const int b    = n0 >> 10;
    const int hw0  = n0 & 1023;
    const float* inbase = inp + (size_t)b * 131072 + hw0;

    // ---- prologue: XP fp32 + A bf16 (swizzled), EN, enc zero ----
    for (int i = t; i < 128 * 64; i += 256) {
        int d2 = i >> 7, p = i & 127;
        float x0 = inbase[(size_t)(2 * d2)     * 1024 + p];
        float x1 = inbase[(size_t)(2 * d2 + 1) * 1024 + p];
        XP[p * 132 + 2 * d2]     = x0;
        XP[p * 132 + 2 * d2 + 1] = x1;
        __nv_bfloat162 bp = __floats2bfloat162_rn(x0, x1);
        *(uint32_t*)(smem + SM_A + swoff(p, 2 * d2)) = *(uint32_t*)&bp;
    }
    for (int i = t; i < 1024; i += 256) EN[i] = g_enorm[i];
    {
        float2* ez = (float2*)(out + OFF_ENC + (size_t)n0 * 1024);
        float2 z = make_float2(0.f, 0.f);
        for (int i = t; i < 65536; i += 256) ez[i] = z;
    }

    // issue B chunks 0 and 1 via cp.async (pre-swizzled bf16 image, linear copy)
    {
        const unsigned char* src0 = g_embbf;
        #pragma unroll
        for (int i = 0; i < 8; i++) {
            uint32_t o = (uint32_t)(t + i * 256) * 16u;
            CP_ASYNC16(sb + SM_B0 + o, src0 + o);
        }
        CP_COMMIT();
        const unsigned char* src1 = g_embbf + 32768;
        #pragma unroll
        for (int i = 0; i < 8; i++) {
            uint32_t o = (uint32_t)(t + i * 256) * 16u;
            CP_ASYNC16(sb + SM_B1 + o, src1 + o);
        }
        CP_COMMIT();
    }
    __syncthreads();

    // ---- A fragments: warp owns rows m0..m0+15, kept in regs for all chunks
    uint32_t af[8][4];
    {
        int m = (wid << 4) + (lane & 15);
        int hi = (lane >> 4) << 3;   // 0 or 8
        #pragma unroll
        for (int ks = 0; ks < 8; ks++)
            ldsm4(af[ks], sb + SM_A + swoff(m, ks * 16 + hi));
    }

    // candidate top-4 per owned row (rows r0, r0+8), disjoint col subset per lane&3
    float ak0 = INFINITY, ak1 = INFINITY, ak2 = INFINITY, ak3 = INFINITY;
    float bk0 = INFINITY, bk1 = INFINITY, bk2 = INFINITY, bk3 = INFINITY;
    int   ai0 = 0, ai1 = 0, ai2 = 0, ai3 = 0;
    int   bi0 = 0, bi1 = 0, bi2 = 0, bi3 = 0;

    const int r_b = lane & 7, seg = lane >> 3;

    for (int j = 0; j < 8; j++) {
        if (j == 7) { CP_WAIT0(); } else { CP_WAIT1(); }
        __syncthreads();
        const uint32_t bbase = sb + ((j & 1) ? SM_B1 : SM_B0);

        #pragma unroll
        for (int nt = 0; nt < 16; nt++) {
            uint32_t brow = bbase + (uint32_t)((nt * 8 + r_b) * 256);
            uint32_t bfr[8][2];
            #pragma unroll
            for (int kp = 0; kp < 4; kp++) {
                uint32_t r4[4];
                ldsm4(r4, brow + (uint32_t)((((kp * 4 + seg) ^ r_b)) << 4));
                bfr[2 * kp][0] = r4[0]; bfr[2 * kp][1] = r4[1];
                bfr[2 * kp + 1][0] = r4[2]; bfr[2 * kp + 1][1] = r4[3];
            }
            float d0 = 0.f, d1 = 0.f, d2 = 0.f, d3 = 0.f;
            #pragma unroll
            for (int ks = 0; ks < 8; ks++)
                mma16816(d0, d1, d2, d3, af[ks], bfr[ks][0], bfr[ks][1]);

            int e = j * 128 + nt * 8 + ((lane & 3) << 1);
            float en0 = EN[e], en1 = EN[e + 1];
            ins4f(fmaf(-2.f, d0, en0), e,     ak0, ai0, ak1, ai1, ak2, ai2, ak3, ai3);
            ins4f(fmaf(-2.f, d1, en1), e + 1, ak0, ai0, ak1, ai1, ak2, ai2, ak3, ai3);
            ins4f(fmaf(-2.f, d2, en0), e,     bk0, bi0, bk1, bi1, bk2, bi2, bk3, bi3);
            ins4f(fmaf(-2.f, d3, en1), e + 1, bk0, bi0, bk1, bi1, bk2, bi2, bk3, bi3);
        }
        __syncthreads();
        if (j + 2 < 8) {
            const unsigned char* src = g_embbf + (size_t)(j + 2) * 32768;
            uint32_t dstb = sb + ((j & 1) ? SM_B1 : SM_B0);
            #pragma unroll
            for (int i = 0; i < 8; i++) {
                uint32_t o = (uint32_t)(t + i * 256) * 16u;
                CP_ASYNC16(dstb + o, src + o);
            }
            CP_COMMIT();
        }
    }

    // ---- stash candidates: 16 per point (4 lanes x top-4, disjoint col subsets)
    {
        int r0 = (wid << 4) + (lane >> 2);
        int c0 = (lane & 3) << 2;
        CI[r0 * 16 + c0 + 0] = ai0;  CI[r0 * 16 + c0 + 1] = ai1;
        CI[r0 * 16 + c0 + 2] = ai2;  CI[r0 * 16 + c0 + 3] = ai3;
        int r1 = r0 + 8;
        CI[r1 * 16 + c0 + 0] = bi0;  CI[r1 * 16 + c0 + 1] = bi1;
        CI[r1 * 16 + c0 + 2] = bi2;  CI[r1 * 16 + c0 + 3] = bi3;
    }
    __syncthreads();

    // ---- exact fp32 rescore: warp w rescoes its 16 points x 16 cands
    {
        const float4* e4 = (const float4*)emb;
        #pragma unroll 4
        for (int it = 0; it < 256; it++) {
            int p = (wid << 4) + (it >> 4);
            int cand = it & 15;
            int idx = CI[p * 16 + cand];
            float4 ev = e4[(size_t)idx * 32 + lane];
            float4 xv = *(const float4*)(XP + p * 132 + (lane << 2));
            float s = fmaf(ev.x, xv.x, fmaf(ev.y, xv.y, fmaf(ev.z, xv.z, ev.w * xv.w)));
            #pragma unroll
            for (int o = 16; o; o >>= 1) s += __shfl_down_sync(0xffffffffu, s, o);
            if (lane == 0)
                PK[p * 16 + cand] = packkey(fmaf(-2.f, s, EN[idx]), idx);
        }
    }
    __syncthreads();

    // ---- exact top-3 per point
    if (t < 128) {
        unsigned long long a0 = ~0ULL, a1 = ~0ULL, a2 = ~0ULL;
        #pragma unroll
        for (int c = 0; c < 16; c++) ins3(PK[t * 16 + c], a0, a1, a2);
        SIDX[t * 3 + 0] = (int)(a0 & 0xffffffffu);
        SIDX[t * 3 + 1] = (int)(a1 & 0xffffffffu);
        SIDX[t * 3 + 2] = (int)(a2 & 0xffffffffu);
    }
    __syncthreads();

    // ---- encodings one-hot (3rd nearest) + counts
    if (t < 128) {
        int i3 = SIDX[t * 3 + 2];
        out[OFF_ENC + (size_t)(n0 + t) * 1024 + i3] = 1.0f;
        atomicAdd(&g_counts[i3], 1);
    }

    // ---- top_k_quantized [3,N,128]; gather nearest rows into ES
    float* ES = (float*)(smem + SM_A);  // [128][132] fp32, reuses A/B region
    for (int k = 0; k < 3; k++) {
        for (int pp = wid; pp < 128; pp += 8) {
            int idx = SIDX[pp * 3 + k];
            const float* er = emb + (size_t)idx * 128;
            size_t ob = OFF_TOPK + ((size_t)k * 32768 + (size_t)(n0 + pp)) * 128;
            #pragma unroll
            for (int jj = 0; jj < 4; jj++) {
                int d = jj * 32 + lane;
                float ev = er[d];
                float x  = XP[pp * 132 + d];
                out[ob + d] = x + (ev - x);
                if (k == 0) ES[pp * 132 + d] = ev;
            }
        }
    }
    __syncthreads();

    // ---- quantized NCHW (nearest) + loss
    float lsum = 0.f;
    {
        int p = t & 127, g = t >> 7;
        size_t qb = OFF_QUANT + (size_t)b * 131072 + (size_t)hw0 + p;
        #pragma unroll 8
        for (int jj = 0; jj < 64; jj++) {
            int d = g * 64 + jj;
            float x  = XP[p * 132 + d];
            float df = ES[p * 132 + d] - x;
            lsum += df * df;
            out[qb + (size_t)d * 1024] = x + df;
        }
    }
    #pragma unroll
    for (int o = 16; o; o >>= 1) lsum += __shfl_down_sync(0xffffffffu, lsum, o);
    if (lane == 0) atomicAdd(&g_loss_sum, lsum);
}

// ---------------------------------------------------------------------------
__global__ void k_final(float* __restrict__ out) {
    __shared__ float red[32];
    int t = threadIdx.x;  // 1024
    float p = (float)g_counts[t] * (1.0f / 32768.0f);
    float v = p * logf(p + 1e-10f);
    #pragma unroll
    for (int o = 16; o; o >>= 1) v += __shfl_down_sync(0xffffffffu, v, o);
    if ((t & 31) == 0) red[t >> 5] = v;
    __syncthreads();
    if (t < 32) {
        float s = red[t];
        #pragma unroll
        for (int o = 16; o; o >>= 1) s += __shfl_down_sync(0xffffffffu, s, o);
        if (t == 0) {
            out[OFF_PERP] = expf(-s);
            out[0] = 0.25f * g_loss_sum * (1.0f / 4194304.0f);
        }
    }
}

// ---------------------------------------------------------------------------
extern "C" void kernel_launch(void* const* d_in, const int* in_sizes, int n_in,
                              void* d_out, int out_size) {
    const float* inp = (const float*)d_in[0];   // [32,128,32,32] fp32
    const float* emb = (const float*)d_in[1];   // [1024,128]    fp32
    float* out = (float*)d_out;

    cudaFuncSetAttribute(k_main, cudaFuncAttributeMaxDynamicSharedMemorySize, SMEM_TOTAL);

    k_init<<<128, 256>>>(emb);
    k_main<<<256, 256, SMEM_TOTAL>>>(inp, emb, out);
    k_final<<<1, 1024>>>(out);
}

// round 6
// speedup vs baseline: 2.3016x; 1.7444x over previous
#include <cuda_runtime.h>
#include <cuda_bf16.h>
#include <cstdint>

// ---------------------------------------------------------------------------
// Output tuple layout (flattened, reference return order)
// ---------------------------------------------------------------------------
static const size_t OFF_QUANT = 1;         // [32,128,32,32]
static const size_t OFF_PERP  = 4194305;   // scalar
static const size_t OFF_ENC   = 4194306;   // [32768,1024]
static const size_t OFF_TOPK  = 37748738;  // [3,32,32,32,128]

__device__ float g_enorm[1024];
__device__ float g_loss_sum;
__device__ int   g_counts[1024];
// bf16 codebook, rows of 256B, pre-swizzled for ldmatrix (chunk c ^= row&7)
__device__ __align__(16) unsigned char g_embbf[1024 * 256];

// ---------------------------------------------------------------------------
// helpers
// ---------------------------------------------------------------------------
__device__ __forceinline__ uint32_t smem_u32(const void* p) {
    uint32_t a;
    asm("{ .reg .u64 t; cvta.to.shared.u64 t, %1; cvt.u32.u64 %0, t; }" : "=r"(a) : "l"(p));
    return a;
}
// swizzled byte offset within a [row][k] bf16 tile (256B rows, 16B chunks)
__device__ __forceinline__ uint32_t swoff(int row, int k) {
    return (uint32_t)(row * 256 + ((((k >> 3) ^ (row & 7)) << 4)) + (k & 7) * 2);
}

#define CP_ASYNC16(dst, src) asm volatile("cp.async.ca.shared.global [%0], [%1], 16;" :: "r"(dst), "l"(src) : "memory")
#define CP_COMMIT()          asm volatile("cp.async.commit_group;" ::: "memory")
#define CP_WAIT1()           asm volatile("cp.async.wait_group 1;" ::: "memory")
#define CP_WAIT0()           asm volatile("cp.async.wait_group 0;" ::: "memory")

__device__ __forceinline__ void ldsm4(uint32_t r[4], uint32_t addr) {
    asm volatile("ldmatrix.sync.aligned.m8n8.x4.shared.b16 {%0,%1,%2,%3}, [%4];"
                 : "=r"(r[0]), "=r"(r[1]), "=r"(r[2]), "=r"(r[3]) : "r"(addr));
}
__device__ __forceinline__ void mma16816(float& d0, float& d1, float& d2, float& d3,
                                         const uint32_t a[4], uint32_t b0, uint32_t b1) {
    asm volatile("mma.sync.aligned.m16n8k16.row.col.f32.bf16.bf16.f32 "
                 "{%0,%1,%2,%3},{%4,%5,%6,%7},{%8,%9},{%0,%1,%2,%3};"
                 : "+f"(d0), "+f"(d1), "+f"(d2), "+f"(d3)
                 : "r"(a[0]), "r"(a[1]), "r"(a[2]), "r"(a[3]), "r"(b0), "r"(b1));
}

__device__ __forceinline__ unsigned long long packkey(float k, int idx) {
    unsigned u = __float_as_uint(k);
    u = (u & 0x80000000u) ? ~u : (u | 0x80000000u);
    return ((unsigned long long)u << 32) | (unsigned)idx;
}
__device__ __forceinline__ void ins3(unsigned long long pk,
                                     unsigned long long& a0, unsigned long long& a1,
                                     unsigned long long& a2) {
    if (pk < a2) {
        if (pk < a1) { a2 = a1; if (pk < a0) { a1 = a0; a0 = pk; } else a1 = pk; }
        else a2 = pk;
    }
}
__device__ __forceinline__ void ins4f(float k, int e,
                                      float& k0, int& i0, float& k1, int& i1,
                                      float& k2, int& i2, float& k3, int& i3) {
    if (k < k3) {
        if (k < k1) {
            k3 = k2; i3 = i2; k2 = k1; i2 = i1;
            if (k < k0) { k1 = k0; i1 = i0; k0 = k; i0 = e; } else { k1 = k; i1 = e; }
        } else {
            if (k < k2) { k3 = k2; i3 = i2; k2 = k; i2 = e; } else { k3 = k; i3 = e; }
        }
    }
}

// ---------------------------------------------------------------------------
// SMEM layout (bytes).  Pool is a union:
//   main loop : B0 (16KB) | B1 (16KB)          cp.async double buffer
//   rescore   : PK u64[128][8] | CI int[128][8]
//   epilogue  : ES half-tile float[128][68]
// ---------------------------------------------------------------------------
#define SM_XP     0u        // float [128 p][132 d]  (67584B)
#define SM_POOL   67584u    // 34816B union
#define SM_B0     (SM_POOL + 0u)
#define SM_B1     (SM_POOL + 16384u)
#define SM_PK     (SM_POOL + 0u)      // u64 [128][8]  (8192)
#define SM_CI     (SM_POOL + 8192u)   // int [128][8]  (4096)
#define SM_ES     (SM_POOL + 0u)      // float [128][68] (34816)
#define SM_EN     102400u   // float [1024]
#define SM_SIDX   106496u   // int [128][3]
#define SMEM_TOTAL 108032u

// ---------------------------------------------------------------------------
__global__ void k_init(const float* __restrict__ emb) {
    int gtid = blockIdx.x * blockDim.x + threadIdx.x;
    int w = gtid >> 5, lane = gtid & 31;
    if (w < 1024) {
        float4 v = ((const float4*)(emb + (size_t)w * 128))[lane];
        __nv_bfloat162 p0 = __floats2bfloat162_rn(v.x, v.y);
        __nv_bfloat162 p1 = __floats2bfloat162_rn(v.z, v.w);
        *(uint2*)(g_embbf + swoff(w, lane * 4)) =
            make_uint2(*(uint32_t*)&p0, *(uint32_t*)&p1);
        float s = v.x*v.x + v.y*v.y + v.z*v.z + v.w*v.w;
        #pragma unroll
        for (int o = 16; o; o >>= 1) s += __shfl_down_sync(0xffffffffu, s, o);
        if (lane == 0) { g_enorm[w] = s; g_counts[w] = 0; }
    }
    if (gtid == 0) g_loss_sum = 0.0f;
}

// ---------------------------------------------------------------------------
__global__ void __launch_bounds__(256, 2) k_main(const float* __restrict__ inp,
                                                 const float* __restrict__ emb,
                                                 float* __restrict__ out) {
    extern __shared__ char smem[];
    const uint32_t sb = smem_u32(smem);
    float* XP = (float*)(smem + SM_XP);
    float* EN = (float*)(smem + SM_EN);
    int*   CI = (int*)(smem + SM_CI);
    unsigned long long* PK = (unsigned long long*)(smem + SM_PK);
    int*   SIDX = (int*)(smem + SM_SIDX);
    float* ES = (float*)(smem + SM_ES);

    const int t    = threadIdx.x;
    const int lane = t & 31;
    const int wid  = t >> 5;
    const int n0   = blockIdx.x * 128;
    const int b    = n0 >> 10;
    const int hw0  = n0 & 1023;
    const float* inbase = inp + (size_t)b * 131072 + hw0;

    // issue B chunks 0,1 via cp.async first (overlaps the XP load)
    #pragma unroll
    for (int i = 0; i < 4; i++) {
        uint32_t o = (uint32_t)(t * 64 + i * 16);
        CP_ASYNC16(sb + SM_B0 + o, g_embbf + o);
    }
    CP_COMMIT();
    #pragma unroll
    for (int i = 0; i < 4; i++) {
        uint32_t o = (uint32_t)(t * 64 + i * 16);
        CP_ASYNC16(sb + SM_B1 + o, g_embbf + 16384 + o);
    }
    CP_COMMIT();

    // ---- prologue: XP fp32, EN, enc zero ----
    for (int i = t; i < 128 * 64; i += 256) {
        int d2 = i >> 7, p = i & 127;
        XP[p * 132 + 2 * d2]     = inbase[(size_t)(2 * d2)     * 1024 + p];
        XP[p * 132 + 2 * d2 + 1] = inbase[(size_t)(2 * d2 + 1) * 1024 + p];
    }
    for (int i = t; i < 1024; i += 256) EN[i] = g_enorm[i];
    {
        float2* ez = (float2*)(out + OFF_ENC + (size_t)n0 * 1024);
        float2 z = make_float2(0.f, 0.f);
        for (int i = t; i < 65536; i += 256) ez[i] = z;
    }
    __syncthreads();

    // ---- A fragments straight from XP (fp32 -> bf16), kept in regs ----
    uint32_t af[8][4];
    {
        int r0 = (wid << 4) + (lane >> 2);
        int kc0 = (lane & 3) * 2;
        #pragma unroll
        for (int ks = 0; ks < 8; ks++) {
            int kb = ks * 16 + kc0;
            float2 a = *(const float2*)(XP + r0 * 132 + kb);
            float2 bb = *(const float2*)(XP + (r0 + 8) * 132 + kb);
            float2 c = *(const float2*)(XP + r0 * 132 + kb + 8);
            float2 d = *(const float2*)(XP + (r0 + 8) * 132 + kb + 8);
            __nv_bfloat162 v0 = __floats2bfloat162_rn(a.x, a.y);
            __nv_bfloat162 v1 = __floats2bfloat162_rn(bb.x, bb.y);
            __nv_bfloat162 v2 = __floats2bfloat162_rn(c.x, c.y);
            __nv_bfloat162 v3 = __floats2bfloat162_rn(d.x, d.y);
            af[ks][0] = *(uint32_t*)&v0;  af[ks][1] = *(uint32_t*)&v1;
            af[ks][2] = *(uint32_t*)&v2;  af[ks][3] = *(uint32_t*)&v3;
        }
    }

    // per-thread candidate top-4 per owned row, over lane's 256-col subset
    float ak0 = INFINITY, ak1 = INFINITY, ak2 = INFINITY, ak3 = INFINITY;
    float bk0 = INFINITY, bk1 = INFINITY, bk2 = INFINITY, bk3 = INFINITY;
    int   ai0 = 0, ai1 = 0, ai2 = 0, ai3 = 0;
    int   bi0 = 0, bi1 = 0, bi2 = 0, bi3 = 0;

    const int r_b = lane & 7, seg = lane >> 3;

    // ---- main loop: 16 chunks of 64 embeddings ----
    for (int j = 0; j < 16; j++) {
        if (j == 15) { CP_WAIT0(); } else { CP_WAIT1(); }
        __syncthreads();
        const uint32_t bbase = sb + ((j & 1) ? SM_B1 : SM_B0);

        #pragma unroll
        for (int nt = 0; nt < 8; nt++) {
            uint32_t brow = bbase + (uint32_t)((nt * 8 + r_b) * 256);
            uint32_t bfr[8][2];
            #pragma unroll
            for (int kp = 0; kp < 4; kp++) {
                uint32_t r4[4];
                ldsm4(r4, brow + (uint32_t)(((kp * 4 + seg) ^ r_b) << 4));
                bfr[2 * kp][0] = r4[0]; bfr[2 * kp][1] = r4[1];
                bfr[2 * kp + 1][0] = r4[2]; bfr[2 * kp + 1][1] = r4[3];
            }
            float d0 = 0.f, d1 = 0.f, d2 = 0.f, d3 = 0.f;
            #pragma unroll
            for (int ks = 0; ks < 8; ks++)
                mma16816(d0, d1, d2, d3, af[ks], bfr[ks][0], bfr[ks][1]);

            int e = j * 64 + nt * 8 + ((lane & 3) << 1);
            float en0 = EN[e], en1 = EN[e + 1];
            ins4f(fmaf(-2.f, d0, en0), e,     ak0, ai0, ak1, ai1, ak2, ai2, ak3, ai3);
            ins4f(fmaf(-2.f, d1, en1), e + 1, ak0, ai0, ak1, ai1, ak2, ai2, ak3, ai3);
            ins4f(fmaf(-2.f, d2, en0), e,     bk0, bi0, bk1, bi1, bk2, bi2, bk3, bi3);
            ins4f(fmaf(-2.f, d3, en1), e + 1, bk0, bi0, bk1, bi1, bk2, bi2, bk3, bi3);
        }
        __syncthreads();
        if (j + 2 < 16) {
            const unsigned char* src = g_embbf + (size_t)(j + 2) * 16384;
            uint32_t dstb = sb + ((j & 1) ? SM_B0 : SM_B1) - SM_B0 + ((j & 1) ? SM_B0 : SM_B1);
            dstb = sb + (((j + 2) & 1) ? SM_B1 : SM_B0);
            #pragma unroll
            for (int i = 0; i < 4; i++) {
                uint32_t o = (uint32_t)(t * 64 + i * 16);
                CP_ASYNC16(dstb + o, src + o);
            }
            CP_COMMIT();
        }
    }

    // ---- merge lane pairs (subset s with s^2) -> top-4 over 512-col halves
    {
        float mk; int mi;
        #define MRG(K,I,L0,L1,L2,L3,M0,M1,M2,M3) \
            mk = __shfl_xor_sync(0xffffffffu, K, 2); \
            mi = __shfl_xor_sync(0xffffffffu, I, 2); \
            ins4f(mk, mi, L0, M0, L1, M1, L2, M2, L3, M3);
        float sa0 = ak0, sa1 = ak1, sa2 = ak2, sa3 = ak3;
        int   ja0 = ai0, ja1 = ai1, ja2 = ai2, ja3 = ai3;
        MRG(sa0, ja0, ak0, ak1, ak2, ak3, ai0, ai1, ai2, ai3)
        MRG(sa1, ja1, ak0, ak1, ak2, ak3, ai0, ai1, ai2, ai3)
        MRG(sa2, ja2, ak0, ak1, ak2, ak3, ai0, ai1, ai2, ai3)
        MRG(sa3, ja3, ak0, ak1, ak2, ak3, ai0, ai1, ai2, ai3)
        float sb0 = bk0, sb1 = bk1, sb2 = bk2, sb3 = bk3;
        int   jb0 = bi0, jb1 = bi1, jb2 = bi2, jb3 = bi3;
        MRG(sb0, jb0, bk0, bk1, bk2, bk3, bi0, bi1, bi2, bi3)
        MRG(sb1, jb1, bk0, bk1, bk2, bk3, bi0, bi1, bi2, bi3)
        MRG(sb2, jb2, bk0, bk1, bk2, bk3, bi0, bi1, bi2, bi3)
        MRG(sb3, jb3, bk0, bk1, bk2, bk3, bi0, bi1, bi2, bi3)
        #undef MRG
    }
    __syncthreads();   // B buffers dead; pool becomes PK/CI

    // ---- stash 8 candidates per point ----
    if ((lane & 3) < 2) {
        int p0 = (wid << 4) + (lane >> 2);
        int c0 = (lane & 3) * 4;
        CI[p0 * 8 + c0 + 0] = ai0;  CI[p0 * 8 + c0 + 1] = ai1;
        CI[p0 * 8 + c0 + 2] = ai2;  CI[p0 * 8 + c0 + 3] = ai3;
        int p1 = p0 + 8;
        CI[p1 * 8 + c0 + 0] = bi0;  CI[p1 * 8 + c0 + 1] = bi1;
        CI[p1 * 8 + c0 + 2] = bi2;  CI[p1 * 8 + c0 + 3] = bi3;
    }
    __syncthreads();

    // ---- exact fp32 rescore: thread = (point, 4 cands) ----
    {
        int p = t >> 1, h2 = t & 1;
        int idx[4]; float acc[4];
        #pragma unroll
        for (int c = 0; c < 4; c++) { idx[c] = CI[p * 8 + h2 * 4 + c]; acc[c] = 0.f; }
        const float4* e4 = (const float4*)emb;
        #pragma unroll 4
        for (int q = 0; q < 32; q++) {
            float4 xv = *(const float4*)(XP + p * 132 + 4 * q);
            #pragma unroll
            for (int c = 0; c < 4; c++) {
                float4 ev = e4[(size_t)idx[c] * 32 + q];
                acc[c] = fmaf(xv.x, ev.x, fmaf(xv.y, ev.y,
                         fmaf(xv.z, ev.z, fmaf(xv.w, ev.w, acc[c]))));
            }
        }
        #pragma unroll
        for (int c = 0; c < 4; c++)
            PK[p * 8 + h2 * 4 + c] = packkey(fmaf(-2.f, acc[c], EN[idx[c]]), idx[c]);
    }
    __syncthreads();

    // ---- exact top-3 per point ----
    if (t < 128) {
        unsigned long long a0 = ~0ULL, a1 = ~0ULL, a2 = ~0ULL;
        #pragma unroll
        for (int c = 0; c < 8; c++) ins3(PK[t * 8 + c], a0, a1, a2);
        SIDX[t * 3 + 0] = (int)(a0 & 0xffffffffu);
        SIDX[t * 3 + 1] = (int)(a1 & 0xffffffffu);
        SIDX[t * 3 + 2] = (int)(a2 & 0xffffffffu);
    }
    __syncthreads();

    // ---- encodings one-hot (3rd nearest) + counts ----
    if (t < 128) {
        int i3 = SIDX[t * 3 + 2];
        out[OFF_ENC + (size_t)(n0 + t) * 1024 + i3] = 1.0f;
        atomicAdd(&g_counts[i3], 1);
    }

    // ---- k=0: topk out + ES half-stage + NCHW + loss, two d-halves ----
    float lsum = 0.f;
    #pragma unroll
    for (int h = 0; h < 2; h++) {
        // gather nearest rows (lane over d), write topk k=0, stage ES half
        for (int pp = wid; pp < 128; pp += 8) {
            int idx = SIDX[pp * 3];
            const float* er = emb + (size_t)idx * 128 + h * 64;
            size_t ob = OFF_TOPK + (size_t)(n0 + pp) * 128 + h * 64;
            #pragma unroll
            for (int jj = 0; jj < 2; jj++) {
                int dd = jj * 32 + lane;
                float ev = er[dd];
                float x  = XP[pp * 132 + h * 64 + dd];
                out[ob + dd] = x + (ev - x);
                ES[pp * 68 + dd] = ev;
            }
        }
        __syncthreads();
        // NCHW half (lane over p -> coalesced) + loss
        {
            int p = t & 127, g = t >> 7;
            size_t qb = OFF_QUANT + (size_t)b * 131072 + (size_t)hw0 + p;
            #pragma unroll 8
            for (int jj = 0; jj < 32; jj++) {
                int dd = g * 32 + jj;
                int d  = h * 64 + dd;
                float x  = XP[p * 132 + d];
                float df = ES[p * 68 + dd] - x;
                lsum += df * df;
                out[qb + (size_t)d * 1024] = x + df;
            }
        }
        __syncthreads();
    }
    #pragma unroll
    for (int o = 16; o; o >>= 1) lsum += __shfl_down_sync(0xffffffffu, lsum, o);
    if (lane == 0) atomicAdd(&g_loss_sum, lsum);

    // ---- k=1,2 topk outputs ----
    #pragma unroll
    for (int k = 1; k < 3; k++) {
        for (int pp = wid; pp < 128; pp += 8) {
            int idx = SIDX[pp * 3 + k];
            const float* er = emb + (size_t)idx * 128;
            size_t ob = OFF_TOPK + ((size_t)k * 32768 + (size_t)(n0 + pp)) * 128;
            #pragma unroll
            for (int jj = 0; jj < 4; jj++) {
                int d = jj * 32 + lane;
                float ev = er[d];
                float x  = XP[pp * 132 + d];
                out[ob + d] = x + (ev - x);
            }
        }
    }
}

// ---------------------------------------------------------------------------
__global__ void k_final(float* __restrict__ out) {
    __shared__ float red[32];
    int t = threadIdx.x;  // 1024
    float p = (float)g_counts[t] * (1.0f / 32768.0f);
    float v = p * logf(p + 1e-10f);
    #pragma unroll
    for (int o = 16; o; o >>= 1) v += __shfl_down_sync(0xffffffffu, v, o);
    if ((t & 31) == 0) red[t >> 5] = v;
    __syncthreads();
    if (t < 32) {
        float s = red[t];
        #pragma unroll
        for (int o = 16; o; o >>= 1) s += __shfl_down_sync(0xffffffffu, s, o);
        if (t == 0) {
            out[OFF_PERP] = expf(-s);
            out[0] = 0.25f * g_loss_sum * (1.0f / 4194304.0f);
        }
    }
}

// ---------------------------------------------------------------------------
extern "C" void kernel_launch(void* const* d_in, const int* in_sizes, int n_in,
                              void* d_out, int out_size) {
    const float* inp = (const float*)d_in[0];   // [32,128,32,32] fp32
    const float* emb = (const float*)d_in[1];   // [1024,128]    fp32
    float* out = (float*)d_out;

    cudaFuncSetAttribute(k_main, cudaFuncAttributeMaxDynamicSharedMemorySize, SMEM_TOTAL);

    k_init<<<128, 256>>>(emb);
    k_main<<<256, 256, SMEM_TOTAL>>>(inp, emb, out);
    k_final<<<1, 1024>>>(out);
}